// round 14
// baseline (speedup 1.0000x reference)
#include <cuda_runtime.h>
#include <cuda_fp16.h>
#include <math.h>
#include <stdint.h>

#define Bb 8
#define Nn 2046
#define Dd 128
#define Jj 128
#define Ll 2
#define Cc 2048
#define BC (Bb*Cc)
#define BN (Bb*Nn)

__device__ float g_feats0[BC*Dd];
__device__ float g_feats1[BC*Dd];
__device__ float g_v[BC*Dd];
__device__ float g_seq[BC*Dd];
__device__ float g_weighted[BC*Dd];
__device__ float g_attnout[BC*Dd];
__device__ float g_num[2*BC*Dd];
__device__ float g_den[2*BC];
__device__ float g_qs[BC];
__device__ float g_ks[BC];
__device__ float g_uq[Dd];
__device__ float g_uk[Dd];
__device__ float g_c[2];
__device__ float g_part[Bb*16*Dd];
__device__ float g_ksmax[Bb];
__device__ uint32_t g_wph[2*448*128];
__device__ uint32_t g_wpl[2*448*128];
__device__ uint32_t g_vph[(BC/2)*128];
__device__ uint32_t g_mbits[Bb*Cc*(Cc/32)];   // 4.2 MB packed mask

// ---- fp16 split helpers ----
__device__ __forceinline__ uint32_t packsplit(float x, float y, uint32_t& lo){
    __half hx = __float2half_rn(x), hy = __float2half_rn(y);
    __half lx = __float2half_rn(x - __half2float(hx));
    __half ly = __float2half_rn(y - __half2float(hy));
    __half2 h = __halves2half2(hx, hy), l2 = __halves2half2(lx, ly);
    lo = *(uint32_t*)&l2;
    return *(uint32_t*)&h;
}
__device__ __forceinline__ uint32_t packh2(float x, float y){
    __half2 h = __halves2half2(__float2half_rn(x), __float2half_rn(y));
    return *(uint32_t*)&h;
}
__device__ __forceinline__ void mma_f16(float c[4], const uint32_t a[4], uint32_t b0, uint32_t b1){
    asm volatile("mma.sync.aligned.m16n8k16.row.col.f32.f16.f16.f32 "
        "{%0,%1,%2,%3}, {%4,%5,%6,%7}, {%8,%9}, {%0,%1,%2,%3};"
        : "+f"(c[0]), "+f"(c[1]), "+f"(c[2]), "+f"(c[3])
        : "r"(a[0]), "r"(a[1]), "r"(a[2]), "r"(a[3]), "r"(b0), "r"(b1));
}

__global__ void copy_ops_kernel(const float* __restrict__ ops, float* __restrict__ feats){
    int idx = blockIdx.x * 256 + threadIdx.x;
    int b = idx / (Nn*Dd);
    int rem = idx - b*(Nn*Dd);
    feats[(size_t)b*Cc*Dd + rem] = ops[idx];
}

// bit-pack extended CxC mask: rows/cols >= Nn are diagonal-only
__global__ void __launch_bounds__(256) packMask_kernel(
    const float* __restrict__ mask, uint32_t* __restrict__ mbits)
{
    int word = blockIdx.x * 8 + (threadIdx.x >> 5);   // 8 warps/block
    int lane = threadIdx.x & 31;
    int b = word / (Cc*Cc/32);
    int rem = word - b*(Cc*Cc/32);
    int i = rem >> 6;              // Cc/32 = 64 words per row
    int j = (rem & 63)*32 + lane;
    bool v;
    if (i < Nn && j < Nn) v = mask[((size_t)b*Nn + i)*Nn + j] > 0.5f;
    else                  v = (i == j);
    uint32_t bits = __ballot_sync(0xffffffffu, v);
    if (lane == 0) mbits[word] = bits;
}

// fused weight packer: both layers, all 4 mats.
__global__ void __launch_bounds__(256) packAllW_kernel(
    const float* __restrict__ aw, const float* __restrict__ sw,
    const float* __restrict__ aow, const float* __restrict__ mw,
    uint32_t* __restrict__ wph, uint32_t* __restrict__ wpl)
{
    int idx = blockIdx.x*256 + threadIdx.x;
    int l = idx / (448*128);
    int r = idx - l*(448*128);
    int kp = r >> 7, c = r & 127;
    const float* src; int ws, kloc;
    if (kp < 64)       { src = aw  + (size_t)l*128*384 + 256; ws = 384; kloc = kp; }
    else if (kp < 256) { src = sw  + (size_t)l*384*128;       ws = 128; kloc = kp - 64; }
    else if (kp < 320) { src = aow + (size_t)l*128*128;       ws = 128; kloc = kp - 256; }
    else               { src = mw  + (size_t)l*256*128;       ws = 128; kloc = kp - 320; }
    float a = src[(size_t)(2*kloc)*ws + c];
    float b = src[(size_t)(2*kloc+1)*ws + c];
    uint32_t lo, hi = packsplit(a, b, lo);
    wph[idx] = hi; wpl[idx] = lo;
}

// fused V pack (fp16 hi only) + column partial sums
__global__ void __launch_bounds__(128) packVmean_kernel(
    const float* __restrict__ v, uint32_t* __restrict__ vph, float* __restrict__ part){
    int b = blockIdx.x, p = blockIdx.y, tx = threadIdx.x;
    int base = b*Cc + p*128;
    float s = 0.f, prev = 0.f;
    #pragma unroll 4
    for (int i = 0; i < 128; ++i) {
        float val = v[((size_t)(base + i))*128 + tx];
        s += val;
        if (i & 1) vph[((size_t)((base + i - 1) >> 1))*128 + tx] = packh2(prev, val);
        prev = val;
    }
    part[(b*16 + p)*128 + tx] = s;
}

__global__ void __launch_bounds__(128) begin_end_kernel(
    const float* __restrict__ src, const int* __restrict__ bidx, const int* __restrict__ eidx,
    const float* __restrict__ Wb, const float* __restrict__ bb,
    const float* __restrict__ We, const float* __restrict__ be, float* __restrict__ dst){
    int b = blockIdx.x, which = blockIdx.y, tx = threadIdx.x;
    const int* idx = which ? eidx : bidx;
    const float* W = which ? We : Wb;
    const float* bias = which ? be : bb;
    __shared__ float avg[128];
    float s = 0.f;
    #pragma unroll 8
    for (int j = 0; j < Jj; ++j) s += src[((size_t)b*Cc + idx[b*Jj + j])*Dd + tx];
    avg[tx] = s * (1.f/Jj);
    __syncthreads();
    float o = 0.f;
    #pragma unroll 8
    for (int dd = 0; dd < Dd; ++dd) o += avg[dd] * W[dd*Dd + tx];
    dst[((size_t)b*Cc + Nn + which)*Dd + tx] = o + bias[tx];
}

// parallel precompute: grid(130) x 32
__global__ void __launch_bounds__(32) precompute2_kernel(
    const float* __restrict__ aw, const float* __restrict__ ab,
    const float* __restrict__ sw, const float* __restrict__ sb,
    float* __restrict__ uq, float* __restrict__ uk, float* __restrict__ cv){
    int id = blockIdx.x, lane = threadIdx.x;
    if (id < 128) {
        float s1 = 0.f, s2 = 0.f;
        #pragma unroll
        for (int e = lane; e < 128; e += 32) {
            s1 += aw[id*384 + e] * sw[e];
            s2 += aw[id*384 + 128 + e] * sw[128 + e];
        }
        #pragma unroll
        for (int off = 16; off; off >>= 1) {
            s1 += __shfl_down_sync(0xffffffffu, s1, off);
            s2 += __shfl_down_sync(0xffffffffu, s2, off);
        }
        if (lane == 0) { uq[id] = s1; uk[id] = s2; }
    } else {
        int which = id - 128;
        float c = 0.f;
        #pragma unroll
        for (int e = lane; e < 128; e += 32)
            c += ab[which*128 + e] * sw[which*128 + e];
        #pragma unroll
        for (int off = 16; off; off >>= 1)
            c += __shfl_down_sync(0xffffffffu, c, off);
        if (lane == 0) cv[which] = which ? (c + sb[0]) : c;
    }
}

__global__ void __launch_bounds__(256) qsks_kernel(
    const float* __restrict__ feats, const float* __restrict__ uq, const float* __restrict__ uk,
    const float* __restrict__ cv, float* __restrict__ qs, float* __restrict__ ks){
    int warp = threadIdx.x >> 5, lane = threadIdx.x & 31;
    int m = blockIdx.x * 8 + warp;
    float4 f = ((const float4*)(feats + (size_t)m*Dd))[lane];
    float4 q4 = ((const float4*)uq)[lane];
    float4 k4 = ((const float4*)uk)[lane];
    float dq = f.x*q4.x + f.y*q4.y + f.z*q4.z + f.w*q4.w;
    float dk = f.x*k4.x + f.y*k4.y + f.z*k4.z + f.w*k4.w;
    #pragma unroll
    for (int off = 16; off; off >>= 1) {
        dq += __shfl_down_sync(0xffffffffu, dq, off);
        dk += __shfl_down_sync(0xffffffffu, dk, off);
    }
    if (lane == 0) { qs[m] = dq + cv[0]; ks[m] = dk + cv[1]; }
}

__global__ void __launch_bounds__(256) ksmax_kernel(const float* __restrict__ ks, float* __restrict__ km){
    int b = blockIdx.x, tx = threadIdx.x;
    __shared__ float sm[256];
    float m = -1e30f;
    for (int j = tx; j < Cc; j += 256) m = fmaxf(m, ks[b*Cc + j]);
    sm[tx] = m; __syncthreads();
    for (int s = 128; s; s >>= 1) { if (tx < s) sm[tx] = fmaxf(sm[tx], sm[tx+s]); __syncthreads(); }
    if (tx == 0) km[b] = sm[0];
}

// ======== fp16 mma GEMM: 128 rows x 64 outs, col-split x2, pre-packed W, 256 thr ========
#define PST2 72
#define PSTR 136
#define ASTRIDE 36

template<int MODE, int KTOT>
__global__ void __launch_bounds__(256) gemm_mma_kernel(
    const float* __restrict__ A, const float* __restrict__ A2,
    const uint32_t* __restrict__ wph, const uint32_t* __restrict__ wpl,
    const float* __restrict__ bias,
    float* __restrict__ out, const int* __restrict__ relations)
{
    __shared__ float As[128*ASTRIDE];
    __shared__ uint32_t Wph[16*PST2];
    __shared__ uint32_t Wpl[16*PST2];
    __shared__ int s_src[3][128];
    __shared__ int s_out[128];

    const int tid = threadIdx.x, w = tid>>5, lane = tid&31;
    const int g = lane>>2, l = lane&3;
    const int m0 = blockIdx.x * 128;
    const int c0 = blockIdx.y * 64;

    if (tid < 128) {
        int m = m0 + tid;
        if (MODE == 1) {
            int b = m >> 11;
            int i = m & 2047;
            if (i < Nn) {
                s_src[0][tid] = b*Cc + i;
                int rp = relations[(size_t)(b*Nn + i)*2 + 0];
                int rs = relations[(size_t)(b*Nn + i)*2 + 1];
                s_src[1][tid] = b*Cc + (rp < 0 ? Nn : rp);
                s_src[2][tid] = b*Cc + (rs < 0 ? Nn + 1 : rs);
                s_out[tid] = m;
            } else {
                s_src[0][tid] = b*Cc; s_src[1][tid] = b*Cc; s_src[2][tid] = b*Cc;
                s_out[tid] = -1;
            }
        } else {
            s_out[tid] = m;
        }
    }
    if (MODE == 1) __syncthreads();

    float acc[8][4];
    #pragma unroll
    for (int nt = 0; nt < 8; ++nt) {
        acc[nt][0]=0.f; acc[nt][1]=0.f; acc[nt][2]=0.f; acc[nt][3]=0.f;
    }

    const int pr = tid>>4, cb4 = (tid&15)*4;
    const int ar = tid>>1, ao = (tid&1)*16;

    uint4 wh4, wl4;
    float4 a0, a1, a2, a3;

    auto loadW = [&](int k0){
        size_t o = ((size_t)(k0>>1) + pr)*128 + c0 + cb4;
        wh4 = *(const uint4*)(wph + o);
        wl4 = *(const uint4*)(wpl + o);
    };
    auto loadA = [&](int k0){
        const float* asrc;
        if (MODE == 0) {
            asrc = A + (size_t)(m0 + ar)*128 + k0 + ao;
        } else if (MODE == 1) {
            int seg = k0 >> 7, col = k0 & 127;
            asrc = A + (size_t)s_src[seg][ar]*128 + col + ao;
        } else {
            int seg = k0 >> 7, col = k0 & 127;
            const float* base = seg ? A2 : A;
            asrc = base + (size_t)(m0 + ar)*128 + col + ao;
        }
        a0 = *(const float4*)(asrc + 0);
        a1 = *(const float4*)(asrc + 4);
        a2 = *(const float4*)(asrc + 8);
        a3 = *(const float4*)(asrc + 12);
    };

    loadW(0); loadA(0);

    for (int k0 = 0; k0 < KTOT; k0 += 32) {
        __syncthreads();
        *(uint4*)(Wph + pr*PST2 + cb4) = wh4;
        *(uint4*)(Wpl + pr*PST2 + cb4) = wl4;
        {
            float* d = As + ar*ASTRIDE + ao;
            *(float4*)(d + 0)  = a0;
            *(float4*)(d + 4)  = a1;
            *(float4*)(d + 8)  = a2;
            *(float4*)(d + 12) = a3;
        }
        __syncthreads();

        if (k0 + 32 < KTOT) { loadW(k0 + 32); loadA(k0 + 32); }

        #pragma unroll
        for (int kc = 0; kc < 2; ++kc) {
            const float* ap  = As + (16*w + g)*ASTRIDE + kc*16;
            const float* ap8 = ap + 8*ASTRIDE;
            float2 x0 = *(const float2*)(ap  + 2*l);
            float2 x1 = *(const float2*)(ap8 + 2*l);
            float2 x2 = *(const float2*)(ap  + 2*l + 8);
            float2 x3 = *(const float2*)(ap8 + 2*l + 8);
            uint32_t ah[4], al[4];
            ah[0] = packsplit(x0.x, x0.y, al[0]);
            ah[1] = packsplit(x1.x, x1.y, al[1]);
            ah[2] = packsplit(x2.x, x2.y, al[2]);
            ah[3] = packsplit(x3.x, x3.y, al[3]);
            const uint32_t* ph  = Wph + (kc*8 + l)*PST2;
            const uint32_t* ph4 = Wph + (kc*8 + l + 4)*PST2;
            const uint32_t* pl  = Wpl + (kc*8 + l)*PST2;
            const uint32_t* pl4 = Wpl + (kc*8 + l + 4)*PST2;
            #pragma unroll
            for (int nt = 0; nt < 8; ++nt) {
                int dcol = nt*8 + g;
                uint32_t bh0 = ph[dcol],  bh1 = ph4[dcol];
                uint32_t bl0 = pl[dcol],  bl1 = pl4[dcol];
                mma_f16(acc[nt], ah, bh0, bh1);
                mma_f16(acc[nt], al, bh0, bh1);
                mma_f16(acc[nt], ah, bl0, bl1);
            }
        }
    }

    const int r0 = 16*w + g;
    const int o0 = s_out[r0], o1 = s_out[r0 + 8];
    float* w0 = out + (size_t)o0*128;
    float* w1 = out + (size_t)o1*128;
    #pragma unroll
    for (int nt = 0; nt < 8; ++nt) {
        int col = c0 + nt*8 + 2*l;
        float b0 = __ldg(bias + col), b1 = __ldg(bias + col + 1);
        if (o0 >= 0) *(float2*)(w0 + col) = make_float2(acc[nt][0]+b0, acc[nt][1]+b1);
        if (o1 >= 0) *(float2*)(w1 + col) = make_float2(acc[nt][2]+b0, acc[nt][3]+b1);
    }
}

// ======== fp16 mma attention, bitmask, 2-product, j-split x2: grid(32,B), 256 thr ========
__global__ void __launch_bounds__(256) attn_mma_kernel(
    const uint32_t* __restrict__ vph,
    const float* __restrict__ qs, const float* __restrict__ ks,
    const float* __restrict__ ksmax, const uint32_t* __restrict__ mbits,
    float* __restrict__ num, float* __restrict__ den)
{
    __shared__ uint32_t Vph[16*PSTR];
    __shared__ float s_ks[32];

    const int b = blockIdx.y;
    const int jc = blockIdx.x & 1;
    const int i0 = (blockIdx.x >> 1) * 128;
    const int tid = threadIdx.x, w = tid>>5, lane = tid&31;
    const int g = lane>>2, l = lane&3;
    const int r0 = 16*w + g, r1 = r0 + 8;
    const int gi0 = i0 + r0, gi1 = i0 + r1;

    const float q0 = qs[b*Cc + gi0];
    const float q1 = qs[b*Cc + gi1];
    const float km = ksmax[b];
    float t0 = q0 + km; t0 = t0 > 0.f ? t0 : 0.01f*t0;
    float t1 = q1 + km; t1 = t1 > 0.f ? t1 : 0.01f*t1;
    const float M0 = fmaxf(0.f, t0);
    const float M1 = fmaxf(0.f, t1);
    const float e0r0 = __expf(-M0);      // masked-entry value for row gi0
    const float e0r1 = __expf(-M1);
    float sum0 = 0.f, sum1 = 0.f;

    const uint32_t* mw0 = mbits + ((size_t)b*Cc + gi0)*64;   // 64 words/row
    const uint32_t* mw1 = mbits + ((size_t)b*Cc + gi1)*64;

    float acc[16][4];
    #pragma unroll
    for (int nt = 0; nt < 16; ++nt) {
        acc[nt][0]=0.f; acc[nt][1]=0.f; acc[nt][2]=0.f; acc[nt][3]=0.f;
    }

    const int pr = tid>>4, cb = (tid&15)*8;
    const int jbeg = jc * 1024, jend = jbeg + 1024;

    uint4 vhA, vhB;
    float ksr = 0.f;
    uint32_t bits0, bits1;
    auto loadV = [&](int j0){
        size_t o = ((size_t)((b*Cc + j0) >> 1) + pr)*128 + cb;
        vhA = *(const uint4*)(vph + o);
        vhB = *(const uint4*)(vph + o + 4);
        if (tid < 32) ksr = ks[b*Cc + j0 + tid];
        bits0 = mw0[j0 >> 5];
        bits1 = mw1[j0 >> 5];
    };
    loadV(jbeg);

    for (int j0 = jbeg; j0 < jend; j0 += 32) {
        __syncthreads();
        *(uint4*)(Vph + pr*PSTR + cb)     = vhA;
        *(uint4*)(Vph + pr*PSTR + cb + 4) = vhB;
        if (tid < 32) s_ks[tid] = ksr;
        uint32_t cb0 = bits0, cb1 = bits1;
        __syncthreads();

        if (j0 + 32 < jend) loadV(j0 + 32);

        #pragma unroll
        for (int kc = 0; kc < 2; ++kc) {
            const int kb = kc*16 + 2*l;
            const float kv0 = s_ks[kb],   kv1 = s_ks[kb+1];
            const float kv8 = s_ks[kb+8], kv9 = s_ks[kb+9];
            float x;
            x = q0 + kv0; x = x>0.f?x:0.01f*x; float p00 = ((cb0>>(kb  ))&1) ? __expf(x - M0) : e0r0;
            x = q0 + kv1; x = x>0.f?x:0.01f*x; float p01 = ((cb0>>(kb+1))&1) ? __expf(x - M0) : e0r0;
            x = q0 + kv8; x = x>0.f?x:0.01f*x; float p08 = ((cb0>>(kb+8))&1) ? __expf(x - M0) : e0r0;
            x = q0 + kv9; x = x>0.f?x:0.01f*x; float p09 = ((cb0>>(kb+9))&1) ? __expf(x - M0) : e0r0;
            x = q1 + kv0; x = x>0.f?x:0.01f*x; float p10 = ((cb1>>(kb  ))&1) ? __expf(x - M1) : e0r1;
            x = q1 + kv1; x = x>0.f?x:0.01f*x; float p11 = ((cb1>>(kb+1))&1) ? __expf(x - M1) : e0r1;
            x = q1 + kv8; x = x>0.f?x:0.01f*x; float p18 = ((cb1>>(kb+8))&1) ? __expf(x - M1) : e0r1;
            x = q1 + kv9; x = x>0.f?x:0.01f*x; float p19 = ((cb1>>(kb+9))&1) ? __expf(x - M1) : e0r1;
            sum0 += p00 + p01 + p08 + p09;
            sum1 += p10 + p11 + p18 + p19;
            uint32_t ah[4], al[4];
            ah[0] = packsplit(p00, p01, al[0]);
            ah[1] = packsplit(p10, p11, al[1]);
            ah[2] = packsplit(p08, p09, al[2]);
            ah[3] = packsplit(p18, p19, al[3]);
            const uint32_t* ph  = Vph + (kc*8 + l)*PSTR;
            const uint32_t* ph4 = Vph + (kc*8 + l + 4)*PSTR;
            #pragma unroll
            for (int nt = 0; nt < 16; ++nt) {
                int dcol = nt*8 + g;
                uint32_t bh0 = ph[dcol],  bh1 = ph4[dcol];
                mma_f16(acc[nt], ah, bh0, bh1);
                mma_f16(acc[nt], al, bh0, bh1);
            }
        }
    }

    sum0 += __shfl_xor_sync(0xffffffffu, sum0, 1);
    sum0 += __shfl_xor_sync(0xffffffffu, sum0, 2);
    sum1 += __shfl_xor_sync(0xffffffffu, sum1, 1);
    sum1 += __shfl_xor_sync(0xffffffffu, sum1, 2);
    if (l == 0) {
        den[(size_t)jc*BC + b*Cc + gi0] = sum0;
        den[(size_t)jc*BC + b*Cc + gi1] = sum1;
    }

    float* n0 = num + (size_t)jc*BC*Dd + ((size_t)(b*Cc + gi0))*128;
    float* n1 = num + (size_t)jc*BC*Dd + ((size_t)(b*Cc + gi1))*128;
    #pragma unroll
    for (int nt = 0; nt < 16; ++nt) {
        int col = nt*8 + 2*l;
        *(float2*)(n0 + col) = make_float2(acc[nt][0], acc[nt][1]);
        *(float2*)(n1 + col) = make_float2(acc[nt][2], acc[nt][3]);
    }
}

__global__ void __launch_bounds__(256) combine_kernel(
    const float* __restrict__ num, const float* __restrict__ den,
    float* __restrict__ wt)
{
    size_t idx = (size_t)blockIdx.x*256 + threadIdx.x;
    int m = (int)(idx >> 7);
    float d = den[m] + den[BC + m];
    wt[idx] = (num[idx] + num[(size_t)BC*Dd + idx]) / d;
}

__global__ void __launch_bounds__(128) fixup_kernel(
    const float* __restrict__ v, const float* __restrict__ part,
    const float* __restrict__ qs, const float* __restrict__ ks,
    float* __restrict__ weighted)
{
    int b = blockIdx.x, which = blockIdx.y, tx = threadIdx.x;
    int r = Nn + which;
    float vsum = 0.f;
    #pragma unroll
    for (int p = 0; p < 16; ++p) vsum += part[(b*16 + p)*128 + tx];
    float s = qs[b*Cc + r] + ks[b*Cc + r];
    s = s > 0.f ? s : 0.01f*s;
    float mx = fmaxf(s, 0.f);
    float es = __expf(s - mx), e0 = __expf(-mx);
    float vr = v[((size_t)(b*Cc + r))*128 + tx];
    float denom = es + (float)(Cc - 1) * e0;
    weighted[((size_t)(b*Cc + r))*128 + tx] = (es*vr + e0*(vsum - vr)) / denom;
}

__global__ void __launch_bounds__(128) mean1_kernel(const float* __restrict__ f, float* __restrict__ part){
    int b = blockIdx.x, p = blockIdx.y, tx = threadIdx.x;
    float s = 0.f;
    #pragma unroll 8
    for (int i = 0; i < Cc/16; ++i) s += f[((size_t)b*Cc + p*(Cc/16) + i)*128 + tx];
    part[(b*16 + p)*128 + tx] = s;
}
__global__ void __launch_bounds__(128) mean2_kernel(const float* __restrict__ part, float* __restrict__ out){
    int b = blockIdx.x, tx = threadIdx.x;
    float s = 0.f;
    #pragma unroll
    for (int p = 0; p < 16; ++p) s += part[(b*16 + p)*128 + tx];
    out[b*128 + tx] = s * (1.f/Cc);
}

extern "C" void kernel_launch(void* const* d_in, const int* in_sizes, int n_in,
                              void* d_out, int out_size)
{
    const float* ops       = (const float*)d_in[0];
    const float* mask      = (const float*)d_in[1];
    const int*   relations = (const int*)d_in[2];
    const int*   begins    = (const int*)d_in[3];
    const int*   ends      = (const int*)d_in[4];
    const float* init_bp_w = (const float*)d_in[5];
    const float* init_bp_b = (const float*)d_in[6];
    const float* init_ep_w = (const float*)d_in[7];
    const float* init_ep_b = (const float*)d_in[8];
    const float* be_bp_w   = (const float*)d_in[9];
    const float* be_bp_b   = (const float*)d_in[10];
    const float* be_ep_w   = (const float*)d_in[11];
    const float* be_ep_b   = (const float*)d_in[12];
    const float* seq_mix_w = (const float*)d_in[13];
    const float* seq_mix_b = (const float*)d_in[14];
    const float* attn_w_w  = (const float*)d_in[15];
    const float* attn_w_b  = (const float*)d_in[16];
    const float* score_w   = (const float*)d_in[17];
    const float* score_b   = (const float*)d_in[18];
    const float* attn_out_w= (const float*)d_in[19];
    const float* attn_out_b= (const float*)d_in[20];
    const float* mix_w     = (const float*)d_in[21];
    const float* mix_b     = (const float*)d_in[22];
    float* out = (float*)d_out;

    float *p_f0,*p_f1,*p_v,*p_seq,*p_wt,*p_ao,*p_qs,*p_ks,*p_uq,*p_uk,*p_c,*p_part,*p_km,*p_num,*p_den;
    uint32_t *p_wph,*p_wpl,*p_vph,*p_mb;
    cudaGetSymbolAddress((void**)&p_f0, g_feats0);
    cudaGetSymbolAddress((void**)&p_f1, g_feats1);
    cudaGetSymbolAddress((void**)&p_v,  g_v);
    cudaGetSymbolAddress((void**)&p_seq, g_seq);
    cudaGetSymbolAddress((void**)&p_wt, g_weighted);
    cudaGetSymbolAddress((void**)&p_ao, g_attnout);
    cudaGetSymbolAddress((void**)&p_qs, g_qs);
    cudaGetSymbolAddress((void**)&p_ks, g_ks);
    cudaGetSymbolAddress((void**)&p_uq, g_uq);
    cudaGetSymbolAddress((void**)&p_uk, g_uk);
    cudaGetSymbolAddress((void**)&p_c,  g_c);
    cudaGetSymbolAddress((void**)&p_part, g_part);
    cudaGetSymbolAddress((void**)&p_km, g_ksmax);
    cudaGetSymbolAddress((void**)&p_num, g_num);
    cudaGetSymbolAddress((void**)&p_den, g_den);
    cudaGetSymbolAddress((void**)&p_wph, g_wph);
    cudaGetSymbolAddress((void**)&p_wpl, g_wpl);
    cudaGetSymbolAddress((void**)&p_vph, g_vph);
    cudaGetSymbolAddress((void**)&p_mb, g_mbits);

    copy_ops_kernel<<<(BN*Dd)/256, 256>>>(ops, p_f0);
    begin_end_kernel<<<dim3(Bb,2), 128>>>(p_f0, begins, ends,
        init_bp_w, init_bp_b, init_ep_w, init_ep_b, p_f0);
    packAllW_kernel<<<(2*448*128)/256, 256>>>(attn_w_w, seq_mix_w, attn_out_w, mix_w,
                                              p_wph, p_wpl);
    packMask_kernel<<<(Bb*Cc*Cc/32)/8, 256>>>(mask, p_mb);

    for (int l = 0; l < Ll; ++l) {
        float* cur = (l == 0) ? p_f0 : p_f1;
        float* nxt = (l == 0) ? p_f1 : (out + Bb*Dd);
        size_t base = (size_t)l*448*128;

        precompute2_kernel<<<130, 32>>>(attn_w_w + (size_t)l*128*384, attn_w_b + (size_t)l*384,
                                        score_w + (size_t)l*256, score_b + l, p_uq, p_uk, p_c);
        qsks_kernel<<<BC/8, 256>>>(cur, p_uq, p_uk, p_c, p_qs, p_ks);
        ksmax_kernel<<<Bb, 256>>>(p_ks, p_km);

        gemm_mma_kernel<0,128><<<dim3(BC/128,2), 256>>>(cur, nullptr,
            p_wph + base, p_wpl + base, attn_w_b + (size_t)l*384 + 256, p_v, nullptr);
        packVmean_kernel<<<dim3(Bb,16), 128>>>(p_v, p_vph, p_part);

        begin_end_kernel<<<dim3(Bb,2), 128>>>(cur, begins, ends,
            be_bp_w + (size_t)l*128*128, be_bp_b + (size_t)l*128,
            be_ep_w + (size_t)l*128*128, be_ep_b + (size_t)l*128, p_seq);

        gemm_mma_kernel<1,384><<<dim3(BC/128,2), 256>>>(cur, nullptr,
            p_wph + base + (size_t)64*128, p_wpl + base + (size_t)64*128,
            seq_mix_b + (size_t)l*128, p_seq, relations);

        attn_mma_kernel<<<dim3(32, Bb), 256>>>(p_vph, p_qs, p_ks, p_km, p_mb, p_num, p_den);
        combine_kernel<<<(BC*Dd)/256, 256>>>(p_num, p_den, p_wt);
        fixup_kernel<<<dim3(Bb,2), 128>>>(p_v, p_part, p_qs, p_ks, p_wt);

        gemm_mma_kernel<0,128><<<dim3(BC/128,2), 256>>>(p_wt, nullptr,
            p_wph + base + (size_t)256*128, p_wpl + base + (size_t)256*128,
            attn_out_b + (size_t)l*128, p_ao, nullptr);

        gemm_mma_kernel<2,256><<<dim3(BC/128,2), 256>>>(p_seq, p_ao,
            p_wph + base + (size_t)320*128, p_wpl + base + (size_t)320*128,
            mix_b + (size_t)l*128, nxt, nullptr);
    }

    mean1_kernel<<<dim3(Bb,16), 128>>>(out + Bb*Dd, p_part);
    mean2_kernel<<<Bb, 128>>>(p_part, out);
}

// round 15
// speedup vs baseline: 1.1660x; 1.1660x over previous
#include <cuda_runtime.h>
#include <cuda_fp16.h>
#include <math.h>
#include <stdint.h>

#define Bb 8
#define Nn 2046
#define Dd 128
#define Jj 128
#define Ll 2
#define Cc 2048
#define BC (Bb*Cc)
#define BN (Bb*Nn)

__device__ float g_feats0[BC*Dd];
__device__ float g_feats1[BC*Dd];
__device__ float g_v[BC*Dd];
__device__ float g_seq[BC*Dd];
__device__ float g_weighted[BC*Dd];
__device__ float g_num[2*BC*Dd];
__device__ float g_den[2*BC];
__device__ float g_qs[BC];
__device__ float g_ks[BC];
__device__ float g_uq[Dd];
__device__ float g_uk[Dd];
__device__ float g_c[2];
__device__ float g_part[Bb*16*Dd];
__device__ float g_ksmax[Bb];
__device__ float g_wf[2*128*128];     // fused ao_w @ mix_bot
__device__ float g_wfb[2*128];        // fused bias
__device__ uint32_t g_wph[2*384*128];
__device__ uint32_t g_wpl[2*384*128];
__device__ uint32_t g_vph[(BC/2)*128];

// ---- fp16 split helpers ----
__device__ __forceinline__ uint32_t packsplit(float x, float y, uint32_t& lo){
    __half hx = __float2half_rn(x), hy = __float2half_rn(y);
    __half lx = __float2half_rn(x - __half2float(hx));
    __half ly = __float2half_rn(y - __half2float(hy));
    __half2 h = __halves2half2(hx, hy), l2 = __halves2half2(lx, ly);
    lo = *(uint32_t*)&l2;
    return *(uint32_t*)&h;
}
__device__ __forceinline__ uint32_t packh2(float x, float y){
    __half2 h = __halves2half2(__float2half_rn(x), __float2half_rn(y));
    return *(uint32_t*)&h;
}
__device__ __forceinline__ void mma_f16(float c[4], const uint32_t a[4], uint32_t b0, uint32_t b1){
    asm volatile("mma.sync.aligned.m16n8k16.row.col.f32.f16.f16.f32 "
        "{%0,%1,%2,%3}, {%4,%5,%6,%7}, {%8,%9}, {%0,%1,%2,%3};"
        : "+f"(c[0]), "+f"(c[1]), "+f"(c[2]), "+f"(c[3])
        : "r"(a[0]), "r"(a[1]), "r"(a[2]), "r"(a[3]), "r"(b0), "r"(b1));
}

__global__ void copy_ops_kernel(const float* __restrict__ ops, float* __restrict__ feats){
    int idx = blockIdx.x * 256 + threadIdx.x;
    int b = idx / (Nn*Dd);
    int rem = idx - b*(Nn*Dd);
    feats[(size_t)b*Cc*Dd + rem] = ops[idx];
}

// Wf = ao_w @ mix_bot; bf = mix_b + ao_b @ mix_bot. grid(129, 2) x 128.
__global__ void __launch_bounds__(128) fuseW_kernel(
    const float* __restrict__ aow, const float* __restrict__ aob,
    const float* __restrict__ mw, const float* __restrict__ mb,
    float* __restrict__ wf, float* __restrict__ wfb)
{
    int k = blockIdx.x, l = blockIdx.y, c = threadIdx.x;
    const float* mbot = mw + (size_t)l*256*128 + 128*128;
    __shared__ float row[128];
    if (k < 128) {
        row[c] = aow[(size_t)l*128*128 + k*128 + c];
        __syncthreads();
        float s = 0.f;
        #pragma unroll 8
        for (int e = 0; e < 128; ++e) s += row[e] * mbot[e*128 + c];
        wf[(size_t)l*128*128 + k*128 + c] = s;
    } else {
        row[c] = aob[l*128 + c];
        __syncthreads();
        float s = mb[l*128 + c];
        #pragma unroll 8
        for (int e = 0; e < 128; ++e) s += row[e] * mbot[e*128 + c];
        wfb[l*128 + c] = s;
    }
}

// fused weight packer. kpair layout per layer: [0,64) v | [64,256) seq | [256,384) mix-fused
__global__ void __launch_bounds__(256) packAllW_kernel(
    const float* __restrict__ aw, const float* __restrict__ sw,
    const float* __restrict__ mw, const float* __restrict__ wf,
    uint32_t* __restrict__ wph, uint32_t* __restrict__ wpl)
{
    int idx = blockIdx.x*256 + threadIdx.x;    // 2*384*128
    int l = idx / (384*128);
    int r = idx - l*(384*128);
    int kp = r >> 7, c = r & 127;
    const float* src; int ws, kloc;
    if (kp < 64)       { src = aw + (size_t)l*128*384 + 256; ws = 384; kloc = kp; }
    else if (kp < 256) { src = sw + (size_t)l*384*128;       ws = 128; kloc = kp - 64; }
    else if (kp < 320) { src = mw + (size_t)l*256*128;       ws = 128; kloc = kp - 256; }  // mix top
    else               { src = wf + (size_t)l*128*128;       ws = 128; kloc = kp - 320; }  // fused
    float a = src[(size_t)(2*kloc)*ws + c];
    float b = src[(size_t)(2*kloc+1)*ws + c];
    uint32_t lo, hi = packsplit(a, b, lo);
    wph[idx] = hi; wpl[idx] = lo;
}

// fused V pack (fp16 hi only) + column partial sums
__global__ void __launch_bounds__(128) packVmean_kernel(
    const float* __restrict__ v, uint32_t* __restrict__ vph, float* __restrict__ part){
    int b = blockIdx.x, p = blockIdx.y, tx = threadIdx.x;
    int base = b*Cc + p*128;
    float s = 0.f, prev = 0.f;
    #pragma unroll 4
    for (int i = 0; i < 128; ++i) {
        float val = v[((size_t)(base + i))*128 + tx];
        s += val;
        if (i & 1) vph[((size_t)((base + i - 1) >> 1))*128 + tx] = packh2(prev, val);
        prev = val;
    }
    part[(b*16 + p)*128 + tx] = s;
}

__global__ void __launch_bounds__(128) begin_end_kernel(
    const float* __restrict__ src, const int* __restrict__ bidx, const int* __restrict__ eidx,
    const float* __restrict__ Wb, const float* __restrict__ bb,
    const float* __restrict__ We, const float* __restrict__ be, float* __restrict__ dst){
    int b = blockIdx.x, which = blockIdx.y, tx = threadIdx.x;
    const int* idx = which ? eidx : bidx;
    const float* W = which ? We : Wb;
    const float* bias = which ? be : bb;
    __shared__ float avg[128];
    float s = 0.f;
    #pragma unroll 8
    for (int j = 0; j < Jj; ++j) s += src[((size_t)b*Cc + idx[b*Jj + j])*Dd + tx];
    avg[tx] = s * (1.f/Jj);
    __syncthreads();
    float o = 0.f;
    #pragma unroll 8
    for (int dd = 0; dd < Dd; ++dd) o += avg[dd] * W[dd*Dd + tx];
    dst[((size_t)b*Cc + Nn + which)*Dd + tx] = o + bias[tx];
}

// parallel precompute: grid(130) x 32
__global__ void __launch_bounds__(32) precompute2_kernel(
    const float* __restrict__ aw, const float* __restrict__ ab,
    const float* __restrict__ sw, const float* __restrict__ sb,
    float* __restrict__ uq, float* __restrict__ uk, float* __restrict__ cv){
    int id = blockIdx.x, lane = threadIdx.x;
    if (id < 128) {
        float s1 = 0.f, s2 = 0.f;
        #pragma unroll
        for (int e = lane; e < 128; e += 32) {
            s1 += aw[id*384 + e] * sw[e];
            s2 += aw[id*384 + 128 + e] * sw[128 + e];
        }
        #pragma unroll
        for (int off = 16; off; off >>= 1) {
            s1 += __shfl_down_sync(0xffffffffu, s1, off);
            s2 += __shfl_down_sync(0xffffffffu, s2, off);
        }
        if (lane == 0) { uq[id] = s1; uk[id] = s2; }
    } else {
        int which = id - 128;
        float c = 0.f;
        #pragma unroll
        for (int e = lane; e < 128; e += 32)
            c += ab[which*128 + e] * sw[which*128 + e];
        #pragma unroll
        for (int off = 16; off; off >>= 1)
            c += __shfl_down_sync(0xffffffffu, c, off);
        if (lane == 0) cv[which] = which ? (c + sb[0]) : c;
    }
}

__global__ void __launch_bounds__(256) qsks_kernel(
    const float* __restrict__ feats, const float* __restrict__ uq, const float* __restrict__ uk,
    const float* __restrict__ cv, float* __restrict__ qs, float* __restrict__ ks){
    int warp = threadIdx.x >> 5, lane = threadIdx.x & 31;
    int m = blockIdx.x * 8 + warp;
    float4 f = ((const float4*)(feats + (size_t)m*Dd))[lane];
    float4 q4 = ((const float4*)uq)[lane];
    float4 k4 = ((const float4*)uk)[lane];
    float dq = f.x*q4.x + f.y*q4.y + f.z*q4.z + f.w*q4.w;
    float dk = f.x*k4.x + f.y*k4.y + f.z*k4.z + f.w*k4.w;
    #pragma unroll
    for (int off = 16; off; off >>= 1) {
        dq += __shfl_down_sync(0xffffffffu, dq, off);
        dk += __shfl_down_sync(0xffffffffu, dk, off);
    }
    if (lane == 0) { qs[m] = dq + cv[0]; ks[m] = dk + cv[1]; }
}

__global__ void __launch_bounds__(256) ksmax_kernel(const float* __restrict__ ks, float* __restrict__ km){
    int b = blockIdx.x, tx = threadIdx.x;
    __shared__ float sm[256];
    float m = -1e30f;
    for (int j = tx; j < Cc; j += 256) m = fmaxf(m, ks[b*Cc + j]);
    sm[tx] = m; __syncthreads();
    for (int s = 128; s; s >>= 1) { if (tx < s) sm[tx] = fmaxf(sm[tx], sm[tx+s]); __syncthreads(); }
    if (tx == 0) km[b] = sm[0];
}

// ======== fp16 mma GEMM: 128 rows x 64 outs, col-split x2, pre-packed W, 256 thr ========
#define PST2 72
#define PSTR 136
#define ASTRIDE 36

template<int MODE, int KTOT>
__global__ void __launch_bounds__(256) gemm_mma_kernel(
    const float* __restrict__ A, const float* __restrict__ A2,
    const uint32_t* __restrict__ wph, const uint32_t* __restrict__ wpl,
    const float* __restrict__ bias,
    float* __restrict__ out, const int* __restrict__ relations)
{
    __shared__ float As[128*ASTRIDE];
    __shared__ uint32_t Wph[16*PST2];
    __shared__ uint32_t Wpl[16*PST2];
    __shared__ int s_src[3][128];
    __shared__ int s_out[128];

    const int tid = threadIdx.x, w = tid>>5, lane = tid&31;
    const int g = lane>>2, l = lane&3;
    const int m0 = blockIdx.x * 128;
    const int c0 = blockIdx.y * 64;

    if (tid < 128) {
        int m = m0 + tid;
        if (MODE == 1) {
            int b = m >> 11;
            int i = m & 2047;
            if (i < Nn) {
                s_src[0][tid] = b*Cc + i;
                int rp = relations[(size_t)(b*Nn + i)*2 + 0];
                int rs = relations[(size_t)(b*Nn + i)*2 + 1];
                s_src[1][tid] = b*Cc + (rp < 0 ? Nn : rp);
                s_src[2][tid] = b*Cc + (rs < 0 ? Nn + 1 : rs);
                s_out[tid] = m;
            } else {
                s_src[0][tid] = b*Cc; s_src[1][tid] = b*Cc; s_src[2][tid] = b*Cc;
                s_out[tid] = -1;
            }
        } else {
            s_out[tid] = m;
        }
    }
    if (MODE == 1) __syncthreads();

    float acc[8][4];
    #pragma unroll
    for (int nt = 0; nt < 8; ++nt) {
        acc[nt][0]=0.f; acc[nt][1]=0.f; acc[nt][2]=0.f; acc[nt][3]=0.f;
    }

    const int pr = tid>>4, cb4 = (tid&15)*4;
    const int ar = tid>>1, ao = (tid&1)*16;

    uint4 wh4, wl4;
    float4 a0, a1, a2, a3;

    auto loadW = [&](int k0){
        size_t o = ((size_t)(k0>>1) + pr)*128 + c0 + cb4;
        wh4 = *(const uint4*)(wph + o);
        wl4 = *(const uint4*)(wpl + o);
    };
    auto loadA = [&](int k0){
        const float* asrc;
        if (MODE == 0) {
            asrc = A + (size_t)(m0 + ar)*128 + k0 + ao;
        } else if (MODE == 1) {
            int seg = k0 >> 7, col = k0 & 127;
            asrc = A + (size_t)s_src[seg][ar]*128 + col + ao;
        } else {
            int seg = k0 >> 7, col = k0 & 127;
            const float* base = seg ? A2 : A;
            asrc = base + (size_t)(m0 + ar)*128 + col + ao;
        }
        a0 = *(const float4*)(asrc + 0);
        a1 = *(const float4*)(asrc + 4);
        a2 = *(const float4*)(asrc + 8);
        a3 = *(const float4*)(asrc + 12);
    };

    loadW(0); loadA(0);

    for (int k0 = 0; k0 < KTOT; k0 += 32) {
        __syncthreads();
        *(uint4*)(Wph + pr*PST2 + cb4) = wh4;
        *(uint4*)(Wpl + pr*PST2 + cb4) = wl4;
        {
            float* d = As + ar*ASTRIDE + ao;
            *(float4*)(d + 0)  = a0;
            *(float4*)(d + 4)  = a1;
            *(float4*)(d + 8)  = a2;
            *(float4*)(d + 12) = a3;
        }
        __syncthreads();

        if (k0 + 32 < KTOT) { loadW(k0 + 32); loadA(k0 + 32); }

        #pragma unroll
        for (int kc = 0; kc < 2; ++kc) {
            const float* ap  = As + (16*w + g)*ASTRIDE + kc*16;
            const float* ap8 = ap + 8*ASTRIDE;
            float2 x0 = *(const float2*)(ap  + 2*l);
            float2 x1 = *(const float2*)(ap8 + 2*l);
            float2 x2 = *(const float2*)(ap  + 2*l + 8);
            float2 x3 = *(const float2*)(ap8 + 2*l + 8);
            uint32_t ah[4], al[4];
            ah[0] = packsplit(x0.x, x0.y, al[0]);
            ah[1] = packsplit(x1.x, x1.y, al[1]);
            ah[2] = packsplit(x2.x, x2.y, al[2]);
            ah[3] = packsplit(x3.x, x3.y, al[3]);
            const uint32_t* ph  = Wph + (kc*8 + l)*PST2;
            const uint32_t* ph4 = Wph + (kc*8 + l + 4)*PST2;
            const uint32_t* pl  = Wpl + (kc*8 + l)*PST2;
            const uint32_t* pl4 = Wpl + (kc*8 + l + 4)*PST2;
            #pragma unroll
            for (int nt = 0; nt < 8; ++nt) {
                int dcol = nt*8 + g;
                uint32_t bh0 = ph[dcol],  bh1 = ph4[dcol];
                uint32_t bl0 = pl[dcol],  bl1 = pl4[dcol];
                mma_f16(acc[nt], ah, bh0, bh1);
                mma_f16(acc[nt], al, bh0, bh1);
                mma_f16(acc[nt], ah, bl0, bl1);
            }
        }
    }

    const int r0 = 16*w + g;
    const int o0 = s_out[r0], o1 = s_out[r0 + 8];
    float* w0 = out + (size_t)o0*128;
    float* w1 = out + (size_t)o1*128;
    #pragma unroll
    for (int nt = 0; nt < 8; ++nt) {
        int col = c0 + nt*8 + 2*l;
        float b0 = __ldg(bias + col), b1 = __ldg(bias + col + 1);
        if (o0 >= 0) *(float2*)(w0 + col) = make_float2(acc[nt][0]+b0, acc[nt][1]+b1);
        if (o1 >= 0) *(float2*)(w1 + col) = make_float2(acc[nt][2]+b0, acc[nt][3]+b1);
    }
}

// ======== fp16 mma attention, 2-product (P split x Vh), j-split x2: grid(32,B), 256 thr ========
__device__ __forceinline__ float pval(float q, float M, float kv, float mv){
    float x = q + kv; x = x > 0.f ? x : 0.01f*x;
    return __expf(x*mv - M);
}
__device__ __forceinline__ float mval(const float* mrow, bool in, int gi, int j){
    return (in && j < Nn) ? __ldg(mrow + j) : ((gi == j) ? 1.f : 0.f);
}

__global__ void __launch_bounds__(256) attn_mma_kernel(
    const uint32_t* __restrict__ vph,
    const float* __restrict__ qs, const float* __restrict__ ks,
    const float* __restrict__ ksmax, const float* __restrict__ mask,
    float* __restrict__ num, float* __restrict__ den)
{
    __shared__ uint32_t Vph[16*PSTR];
    __shared__ float s_ks[32];

    const int b = blockIdx.y;
    const int jc = blockIdx.x & 1;
    const int i0 = (blockIdx.x >> 1) * 128;
    const int tid = threadIdx.x, w = tid>>5, lane = tid&31;
    const int g = lane>>2, l = lane&3;
    const int r0 = 16*w + g, r1 = r0 + 8;
    const int gi0 = i0 + r0, gi1 = i0 + r1;

    const float q0 = qs[b*Cc + gi0];
    const float q1 = qs[b*Cc + gi1];
    const float km = ksmax[b];
    float t0 = q0 + km; t0 = t0 > 0.f ? t0 : 0.01f*t0;
    float t1 = q1 + km; t1 = t1 > 0.f ? t1 : 0.01f*t1;
    const float M0 = fmaxf(0.f, t0);
    const float M1 = fmaxf(0.f, t1);
    float sum0 = 0.f, sum1 = 0.f;

    const float* mrow0 = mask + (size_t)b*Nn*Nn + (size_t)gi0*Nn;
    const float* mrow1 = mask + (size_t)b*Nn*Nn + (size_t)gi1*Nn;
    const bool in0 = gi0 < Nn, in1 = gi1 < Nn;

    float acc[16][4];
    #pragma unroll
    for (int nt = 0; nt < 16; ++nt) {
        acc[nt][0]=0.f; acc[nt][1]=0.f; acc[nt][2]=0.f; acc[nt][3]=0.f;
    }

    const int pr = tid>>4, cb = (tid&15)*8;
    const int jbeg = jc * 1024, jend = jbeg + 1024;

    uint4 vhA, vhB;
    float ksr = 0.f;
    auto loadV = [&](int j0){
        size_t o = ((size_t)((b*Cc + j0) >> 1) + pr)*128 + cb;
        vhA = *(const uint4*)(vph + o);
        vhB = *(const uint4*)(vph + o + 4);
        if (tid < 32) ksr = ks[b*Cc + j0 + tid];
    };
    loadV(jbeg);

    for (int j0 = jbeg; j0 < jend; j0 += 32) {
        __syncthreads();
        *(uint4*)(Vph + pr*PSTR + cb)     = vhA;
        *(uint4*)(Vph + pr*PSTR + cb + 4) = vhB;
        if (tid < 32) s_ks[tid] = ksr;
        __syncthreads();

        if (j0 + 32 < jend) loadV(j0 + 32);

        float m0v[8], m1v[8];
        #pragma unroll
        for (int kc = 0; kc < 2; ++kc) {
            int ja = j0 + kc*16 + 2*l;
            m0v[kc*4+0] = mval(mrow0, in0, gi0, ja);
            m0v[kc*4+1] = mval(mrow0, in0, gi0, ja+1);
            m0v[kc*4+2] = mval(mrow0, in0, gi0, ja+8);
            m0v[kc*4+3] = mval(mrow0, in0, gi0, ja+9);
            m1v[kc*4+0] = mval(mrow1, in1, gi1, ja);
            m1v[kc*4+1] = mval(mrow1, in1, gi1, ja+1);
            m1v[kc*4+2] = mval(mrow1, in1, gi1, ja+8);
            m1v[kc*4+3] = mval(mrow1, in1, gi1, ja+9);
        }

        #pragma unroll
        for (int kc = 0; kc < 2; ++kc) {
            const int kb = kc*16 + 2*l;
            const float kv0 = s_ks[kb],   kv1 = s_ks[kb+1];
            const float kv8 = s_ks[kb+8], kv9 = s_ks[kb+9];
            float p00 = pval(q0, M0, kv0, m0v[kc*4+0]);
            float p01 = pval(q0, M0, kv1, m0v[kc*4+1]);
            float p08 = pval(q0, M0, kv8, m0v[kc*4+2]);
            float p09 = pval(q0, M0, kv9, m0v[kc*4+3]);
            float p10 = pval(q1, M1, kv0, m1v[kc*4+0]);
            float p11 = pval(q1, M1, kv1, m1v[kc*4+1]);
            float p18 = pval(q1, M1, kv8, m1v[kc*4+2]);
            float p19 = pval(q1, M1, kv9, m1v[kc*4+3]);
            sum0 += p00 + p01 + p08 + p09;
            sum1 += p10 + p11 + p18 + p19;
            uint32_t ah[4], al[4];
            ah[0] = packsplit(p00, p01, al[0]);
            ah[1] = packsplit(p10, p11, al[1]);
            ah[2] = packsplit(p08, p09, al[2]);
            ah[3] = packsplit(p18, p19, al[3]);
            const uint32_t* ph  = Vph + (kc*8 + l)*PSTR;
            const uint32_t* ph4 = Vph + (kc*8 + l + 4)*PSTR;
            #pragma unroll
            for (int nt = 0; nt < 16; ++nt) {
                int dcol = nt*8 + g;
                uint32_t bh0 = ph[dcol],  bh1 = ph4[dcol];
                mma_f16(acc[nt], ah, bh0, bh1);
                mma_f16(acc[nt], al, bh0, bh1);
            }
        }
    }

    sum0 += __shfl_xor_sync(0xffffffffu, sum0, 1);
    sum0 += __shfl_xor_sync(0xffffffffu, sum0, 2);
    sum1 += __shfl_xor_sync(0xffffffffu, sum1, 1);
    sum1 += __shfl_xor_sync(0xffffffffu, sum1, 2);
    if (l == 0) {
        den[(size_t)jc*BC + b*Cc + gi0] = sum0;
        den[(size_t)jc*BC + b*Cc + gi1] = sum1;
    }

    float* n0 = num + (size_t)jc*BC*Dd + ((size_t)(b*Cc + gi0))*128;
    float* n1 = num + (size_t)jc*BC*Dd + ((size_t)(b*Cc + gi1))*128;
    #pragma unroll
    for (int nt = 0; nt < 16; ++nt) {
        int col = nt*8 + 2*l;
        *(float2*)(n0 + col) = make_float2(acc[nt][0], acc[nt][1]);
        *(float2*)(n1 + col) = make_float2(acc[nt][2], acc[nt][3]);
    }
}

__global__ void __launch_bounds__(256) combine_kernel(
    const float* __restrict__ num, const float* __restrict__ den,
    float* __restrict__ wt)
{
    size_t idx = (size_t)blockIdx.x*256 + threadIdx.x;
    int m = (int)(idx >> 7);
    float d = den[m] + den[BC + m];
    wt[idx] = (num[idx] + num[(size_t)BC*Dd + idx]) / d;
}

__global__ void __launch_bounds__(128) fixup_kernel(
    const float* __restrict__ v, const float* __restrict__ part,
    const float* __restrict__ qs, const float* __restrict__ ks,
    float* __restrict__ weighted)
{
    int b = blockIdx.x, which = blockIdx.y, tx = threadIdx.x;
    int r = Nn + which;
    float vsum = 0.f;
    #pragma unroll
    for (int p = 0; p < 16; ++p) vsum += part[(b*16 + p)*128 + tx];
    float s = qs[b*Cc + r] + ks[b*Cc + r];
    s = s > 0.f ? s : 0.01f*s;
    float mx = fmaxf(s, 0.f);
    float es = __expf(s - mx), e0 = __expf(-mx);
    float vr = v[((size_t)(b*Cc + r))*128 + tx];
    float denom = es + (float)(Cc - 1) * e0;
    weighted[((size_t)(b*Cc + r))*128 + tx] = (es*vr + e0*(vsum - vr)) / denom;
}

__global__ void __launch_bounds__(128) mean1_kernel(const float* __restrict__ f, float* __restrict__ part){
    int b = blockIdx.x, p = blockIdx.y, tx = threadIdx.x;
    float s = 0.f;
    #pragma unroll 8
    for (int i = 0; i < Cc/16; ++i) s += f[((size_t)b*Cc + p*(Cc/16) + i)*128 + tx];
    part[(b*16 + p)*128 + tx] = s;
}
__global__ void __launch_bounds__(128) mean2_kernel(const float* __restrict__ part, float* __restrict__ out){
    int b = blockIdx.x, tx = threadIdx.x;
    float s = 0.f;
    #pragma unroll
    for (int p = 0; p < 16; ++p) s += part[(b*16 + p)*128 + tx];
    out[b*128 + tx] = s * (1.f/Cc);
}

extern "C" void kernel_launch(void* const* d_in, const int* in_sizes, int n_in,
                              void* d_out, int out_size)
{
    const float* ops       = (const float*)d_in[0];
    const float* mask      = (const float*)d_in[1];
    const int*   relations = (const int*)d_in[2];
    const int*   begins    = (const int*)d_in[3];
    const int*   ends      = (const int*)d_in[4];
    const float* init_bp_w = (const float*)d_in[5];
    const float* init_bp_b = (const float*)d_in[6];
    const float* init_ep_w = (const float*)d_in[7];
    const float* init_ep_b = (const float*)d_in[8];
    const float* be_bp_w   = (const float*)d_in[9];
    const float* be_bp_b   = (const float*)d_in[10];
    const float* be_ep_w   = (const float*)d_in[11];
    const float* be_ep_b   = (const float*)d_in[12];
    const float* seq_mix_w = (const float*)d_in[13];
    const float* seq_mix_b = (const float*)d_in[14];
    const float* attn_w_w  = (const float*)d_in[15];
    const float* attn_w_b  = (const float*)d_in[16];
    const float* score_w   = (const float*)d_in[17];
    const float* score_b   = (const float*)d_in[18];
    const float* attn_out_w= (const float*)d_in[19];
    const float* attn_out_b= (const float*)d_in[20];
    const float* mix_w     = (const float*)d_in[21];
    const float* mix_b     = (const float*)d_in[22];
    float* out = (float*)d_out;

    float *p_f0,*p_f1,*p_v,*p_seq,*p_wt,*p_qs,*p_ks,*p_uq,*p_uk,*p_c,*p_part,*p_km,*p_num,*p_den,*p_wf,*p_wfb;
    uint32_t *p_wph,*p_wpl,*p_vph;
    cudaGetSymbolAddress((void**)&p_f0, g_feats0);
    cudaGetSymbolAddress((void**)&p_f1, g_feats1);
    cudaGetSymbolAddress((void**)&p_v,  g_v);
    cudaGetSymbolAddress((void**)&p_seq, g_seq);
    cudaGetSymbolAddress((void**)&p_wt, g_weighted);
    cudaGetSymbolAddress((void**)&p_qs, g_qs);
    cudaGetSymbolAddress((void**)&p_ks, g_ks);
    cudaGetSymbolAddress((void**)&p_uq, g_uq);
    cudaGetSymbolAddress((void**)&p_uk, g_uk);
    cudaGetSymbolAddress((void**)&p_c,  g_c);
    cudaGetSymbolAddress((void**)&p_part, g_part);
    cudaGetSymbolAddress((void**)&p_km, g_ksmax);
    cudaGetSymbolAddress((void**)&p_num, g_num);
    cudaGetSymbolAddress((void**)&p_den, g_den);
    cudaGetSymbolAddress((void**)&p_wf, g_wf);
    cudaGetSymbolAddress((void**)&p_wfb, g_wfb);
    cudaGetSymbolAddress((void**)&p_wph, g_wph);
    cudaGetSymbolAddress((void**)&p_wpl, g_wpl);
    cudaGetSymbolAddress((void**)&p_vph, g_vph);

    copy_ops_kernel<<<(BN*Dd)/256, 256>>>(ops, p_f0);
    begin_end_kernel<<<dim3(Bb,2), 128>>>(p_f0, begins, ends,
        init_bp_w, init_bp_b, init_ep_w, init_ep_b, p_f0);
    fuseW_kernel<<<dim3(129,2), 128>>>(attn_out_w, attn_out_b, mix_w, mix_b, p_wf, p_wfb);
    packAllW_kernel<<<(2*384*128)/256, 256>>>(attn_w_w, seq_mix_w, mix_w, p_wf,
                                              p_wph, p_wpl);

    for (int l = 0; l < Ll; ++l) {
        float* cur = (l == 0) ? p_f0 : p_f1;
        float* nxt = (l == 0) ? p_f1 : (out + Bb*Dd);
        size_t base = (size_t)l*384*128;

        precompute2_kernel<<<130, 32>>>(attn_w_w + (size_t)l*128*384, attn_w_b + (size_t)l*384,
                                        score_w + (size_t)l*256, score_b + l, p_uq, p_uk, p_c);
        qsks_kernel<<<BC/8, 256>>>(cur, p_uq, p_uk, p_c, p_qs, p_ks);
        ksmax_kernel<<<Bb, 256>>>(p_ks, p_km);

        gemm_mma_kernel<0,128><<<dim3(BC/128,2), 256>>>(cur, nullptr,
            p_wph + base, p_wpl + base, attn_w_b + (size_t)l*384 + 256, p_v, nullptr);
        packVmean_kernel<<<dim3(Bb,16), 128>>>(p_v, p_vph, p_part);

        begin_end_kernel<<<dim3(Bb,2), 128>>>(cur, begins, ends,
            be_bp_w + (size_t)l*128*128, be_bp_b + (size_t)l*128,
            be_ep_w + (size_t)l*128*128, be_ep_b + (size_t)l*128, p_seq);

        gemm_mma_kernel<1,384><<<dim3(BC/128,2), 256>>>(cur, nullptr,
            p_wph + base + (size_t)64*128, p_wpl + base + (size_t)64*128,
            seq_mix_b + (size_t)l*128, p_seq, relations);

        attn_mma_kernel<<<dim3(32, Bb), 256>>>(p_vph, p_qs, p_ks, p_km, mask, p_num, p_den);
        combine_kernel<<<(BC*Dd)/256, 256>>>(p_num, p_den, p_wt);
        fixup_kernel<<<dim3(Bb,2), 128>>>(p_v, p_part, p_qs, p_ks, p_wt);

        // fused: feats_next = seq @ mix_top + wt @ (ao_w @ mix_bot) + bfused
        gemm_mma_kernel<2,256><<<dim3(BC/128,2), 256>>>(p_seq, p_wt,
            p_wph + base + (size_t)256*128, p_wpl + base + (size_t)256*128,
            p_wfb + l*128, nxt, nullptr);
    }

    mean1_kernel<<<dim3(Bb,16), 128>>>(out + Bb*Dd, p_part);
    mean2_kernel<<<Bb, 128>>>(p_part, out);
}

// round 16
// speedup vs baseline: 1.2339x; 1.0582x over previous
#include <cuda_runtime.h>
#include <cuda_fp16.h>
#include <math.h>
#include <stdint.h>

#define Bb 8
#define Nn 2046
#define Dd 128
#define Jj 128
#define Ll 2
#define Cc 2048
#define BC (Bb*Cc)
#define BN (Bb*Nn)

__device__ float g_feats0[BC*Dd];
__device__ float g_feats1[BC*Dd];
__device__ float g_v[BC*Dd];
__device__ float g_seq[BC*Dd];
__device__ float g_weighted[BC*Dd];
__device__ float g_num[2*BC*Dd];
__device__ float g_den[2*BC];
__device__ float g_qs[BC];
__device__ float g_ks[BC];
__device__ float g_uq[Dd];
__device__ float g_uk[Dd];
__device__ float g_c[2];
__device__ float g_part[Bb*16*Dd];
__device__ float g_ksmax[Bb];
__device__ float g_wf[2*128*128];
__device__ float g_wfb[2*128];
__device__ uint32_t g_wph[2*384*128];
__device__ uint32_t g_wpl[2*384*128];
__device__ uint32_t g_vph[(BC/2)*128];

// ---- fp16 helpers ----
__device__ __forceinline__ uint32_t packsplit(float x, float y, uint32_t& lo){
    __half hx = __float2half_rn(x), hy = __float2half_rn(y);
    __half lx = __float2half_rn(x - __half2float(hx));
    __half ly = __float2half_rn(y - __half2float(hy));
    __half2 h = __halves2half2(hx, hy), l2 = __halves2half2(lx, ly);
    lo = *(uint32_t*)&l2;
    return *(uint32_t*)&h;
}
__device__ __forceinline__ uint32_t packh2(float x, float y){
    __half2 h = __halves2half2(__float2half_rn(x), __float2half_rn(y));
    return *(uint32_t*)&h;
}
__device__ __forceinline__ void mma_f16(float c[4], const uint32_t a[4], uint32_t b0, uint32_t b1){
    asm volatile("mma.sync.aligned.m16n8k16.row.col.f32.f16.f16.f32 "
        "{%0,%1,%2,%3}, {%4,%5,%6,%7}, {%8,%9}, {%0,%1,%2,%3};"
        : "+f"(c[0]), "+f"(c[1]), "+f"(c[2]), "+f"(c[3])
        : "r"(a[0]), "r"(a[1]), "r"(a[2]), "r"(a[3]), "r"(b0), "r"(b1));
}

__global__ void copy_ops_kernel(const float* __restrict__ ops, float* __restrict__ feats){
    int idx = blockIdx.x * 256 + threadIdx.x;
    int b = idx / (Nn*Dd);
    int rem = idx - b*(Nn*Dd);
    feats[(size_t)b*Cc*Dd + rem] = ops[idx];
}

// Wf = ao_w @ mix_bot; bf = mix_b + ao_b @ mix_bot. grid(129, 2) x 128.
__global__ void __launch_bounds__(128) fuseW_kernel(
    const float* __restrict__ aow, const float* __restrict__ aob,
    const float* __restrict__ mw, const float* __restrict__ mb,
    float* __restrict__ wf, float* __restrict__ wfb)
{
    int k = blockIdx.x, l = blockIdx.y, c = threadIdx.x;
    const float* mbot = mw + (size_t)l*256*128 + 128*128;
    __shared__ float row[128];
    if (k < 128) {
        row[c] = aow[(size_t)l*128*128 + k*128 + c];
        __syncthreads();
        float s = 0.f;
        #pragma unroll 8
        for (int e = 0; e < 128; ++e) s += row[e] * mbot[e*128 + c];
        wf[(size_t)l*128*128 + k*128 + c] = s;
    } else {
        row[c] = aob[l*128 + c];
        __syncthreads();
        float s = mb[l*128 + c];
        #pragma unroll 8
        for (int e = 0; e < 128; ++e) s += row[e] * mbot[e*128 + c];
        wfb[l*128 + c] = s;
    }
}

// fused weight packer. kpair layout per layer: [0,64) v | [64,256) seq | [256,384) mix-fused
__global__ void __launch_bounds__(256) packAllW_kernel(
    const float* __restrict__ aw, const float* __restrict__ sw,
    const float* __restrict__ mw, const float* __restrict__ wf,
    uint32_t* __restrict__ wph, uint32_t* __restrict__ wpl)
{
    int idx = blockIdx.x*256 + threadIdx.x;
    int l = idx / (384*128);
    int r = idx - l*(384*128);
    int kp = r >> 7, c = r & 127;
    const float* src; int ws, kloc;
    if (kp < 64)       { src = aw + (size_t)l*128*384 + 256; ws = 384; kloc = kp; }
    else if (kp < 256) { src = sw + (size_t)l*384*128;       ws = 128; kloc = kp - 64; }
    else if (kp < 320) { src = mw + (size_t)l*256*128;       ws = 128; kloc = kp - 256; }
    else               { src = wf + (size_t)l*128*128;       ws = 128; kloc = kp - 320; }
    float a = src[(size_t)(2*kloc)*ws + c];
    float b = src[(size_t)(2*kloc+1)*ws + c];
    uint32_t lo, hi = packsplit(a, b, lo);
    wph[idx] = hi; wpl[idx] = lo;
}

// fused V pack (fp16 hi only) + column partial sums
__global__ void __launch_bounds__(128) packVmean_kernel(
    const float* __restrict__ v, uint32_t* __restrict__ vph, float* __restrict__ part){
    int b = blockIdx.x, p = blockIdx.y, tx = threadIdx.x;
    int base = b*Cc + p*128;
    float s = 0.f, prev = 0.f;
    #pragma unroll 4
    for (int i = 0; i < 128; ++i) {
        float val = v[((size_t)(base + i))*128 + tx];
        s += val;
        if (i & 1) vph[((size_t)((base + i - 1) >> 1))*128 + tx] = packh2(prev, val);
        prev = val;
    }
    part[(b*16 + p)*128 + tx] = s;
}

__global__ void __launch_bounds__(128) begin_end_kernel(
    const float* __restrict__ src, const int* __restrict__ bidx, const int* __restrict__ eidx,
    const float* __restrict__ Wb, const float* __restrict__ bb,
    const float* __restrict__ We, const float* __restrict__ be, float* __restrict__ dst){
    int b = blockIdx.x, which = blockIdx.y, tx = threadIdx.x;
    const int* idx = which ? eidx : bidx;
    const float* W = which ? We : Wb;
    const float* bias = which ? be : bb;
    __shared__ float avg[128];
    float s = 0.f;
    #pragma unroll 8
    for (int j = 0; j < Jj; ++j) s += src[((size_t)b*Cc + idx[b*Jj + j])*Dd + tx];
    avg[tx] = s * (1.f/Jj);
    __syncthreads();
    float o = 0.f;
    #pragma unroll 8
    for (int dd = 0; dd < Dd; ++dd) o += avg[dd] * W[dd*Dd + tx];
    dst[((size_t)b*Cc + Nn + which)*Dd + tx] = o + bias[tx];
}

// parallel precompute: grid(130) x 32
__global__ void __launch_bounds__(32) precompute2_kernel(
    const float* __restrict__ aw, const float* __restrict__ ab,
    const float* __restrict__ sw, const float* __restrict__ sb,
    float* __restrict__ uq, float* __restrict__ uk, float* __restrict__ cv){
    int id = blockIdx.x, lane = threadIdx.x;
    if (id < 128) {
        float s1 = 0.f, s2 = 0.f;
        #pragma unroll
        for (int e = lane; e < 128; e += 32) {
            s1 += aw[id*384 + e] * sw[e];
            s2 += aw[id*384 + 128 + e] * sw[128 + e];
        }
        #pragma unroll
        for (int off = 16; off; off >>= 1) {
            s1 += __shfl_down_sync(0xffffffffu, s1, off);
            s2 += __shfl_down_sync(0xffffffffu, s2, off);
        }
        if (lane == 0) { uq[id] = s1; uk[id] = s2; }
    } else {
        int which = id - 128;
        float c = 0.f;
        #pragma unroll
        for (int e = lane; e < 128; e += 32)
            c += ab[which*128 + e] * sw[which*128 + e];
        #pragma unroll
        for (int off = 16; off; off >>= 1)
            c += __shfl_down_sync(0xffffffffu, c, off);
        if (lane == 0) cv[which] = which ? (c + sb[0]) : c;
    }
}

__global__ void __launch_bounds__(256) qsks_kernel(
    const float* __restrict__ feats, const float* __restrict__ uq, const float* __restrict__ uk,
    const float* __restrict__ cv, float* __restrict__ qs, float* __restrict__ ks){
    int warp = threadIdx.x >> 5, lane = threadIdx.x & 31;
    int m = blockIdx.x * 8 + warp;
    float4 f = ((const float4*)(feats + (size_t)m*Dd))[lane];
    float4 q4 = ((const float4*)uq)[lane];
    float4 k4 = ((const float4*)uk)[lane];
    float dq = f.x*q4.x + f.y*q4.y + f.z*q4.z + f.w*q4.w;
    float dk = f.x*k4.x + f.y*k4.y + f.z*k4.z + f.w*k4.w;
    #pragma unroll
    for (int off = 16; off; off >>= 1) {
        dq += __shfl_down_sync(0xffffffffu, dq, off);
        dk += __shfl_down_sync(0xffffffffu, dk, off);
    }
    if (lane == 0) { qs[m] = dq + cv[0]; ks[m] = dk + cv[1]; }
}

__global__ void __launch_bounds__(256) ksmax_kernel(const float* __restrict__ ks, float* __restrict__ km){
    int b = blockIdx.x, tx = threadIdx.x;
    __shared__ float sm[256];
    float m = -1e30f;
    for (int j = tx; j < Cc; j += 256) m = fmaxf(m, ks[b*Cc + j]);
    sm[tx] = m; __syncthreads();
    for (int s = 128; s; s >>= 1) { if (tx < s) sm[tx] = fmaxf(sm[tx], sm[tx+s]); __syncthreads(); }
    if (tx == 0) km[b] = sm[0];
}

// ======== fp16 mma GEMM: 128 rows x 64 outs, col-split x2, pre-packed W, 256 thr ========
#define PST2 72
#define PSTR 136
#define ASTRIDE 36

template<int MODE, int KTOT>
__global__ void __launch_bounds__(256) gemm_mma_kernel(
    const float* __restrict__ A, const float* __restrict__ A2,
    const uint32_t* __restrict__ wph, const uint32_t* __restrict__ wpl,
    const float* __restrict__ bias,
    float* __restrict__ out, const int* __restrict__ relations)
{
    __shared__ float As[128*ASTRIDE];
    __shared__ uint32_t Wph[16*PST2];
    __shared__ uint32_t Wpl[16*PST2];
    __shared__ int s_src[3][128];
    __shared__ int s_out[128];

    const int tid = threadIdx.x, w = tid>>5, lane = tid&31;
    const int g = lane>>2, l = lane&3;
    const int m0 = blockIdx.x * 128;
    const int c0 = blockIdx.y * 64;

    if (tid < 128) {
        int m = m0 + tid;
        if (MODE == 1) {
            int b = m >> 11;
            int i = m & 2047;
            if (i < Nn) {
                s_src[0][tid] = b*Cc + i;
                int rp = relations[(size_t)(b*Nn + i)*2 + 0];
                int rs = relations[(size_t)(b*Nn + i)*2 + 1];
                s_src[1][tid] = b*Cc + (rp < 0 ? Nn : rp);
                s_src[2][tid] = b*Cc + (rs < 0 ? Nn + 1 : rs);
                s_out[tid] = m;
            } else {
                s_src[0][tid] = b*Cc; s_src[1][tid] = b*Cc; s_src[2][tid] = b*Cc;
                s_out[tid] = -1;
            }
        } else {
            s_out[tid] = m;
        }
    }
    if (MODE == 1) __syncthreads();

    float acc[8][4];
    #pragma unroll
    for (int nt = 0; nt < 8; ++nt) {
        acc[nt][0]=0.f; acc[nt][1]=0.f; acc[nt][2]=0.f; acc[nt][3]=0.f;
    }

    const int pr = tid>>4, cb4 = (tid&15)*4;
    const int ar = tid>>1, ao = (tid&1)*16;

    uint4 wh4, wl4;
    float4 a0, a1, a2, a3;

    auto loadW = [&](int k0){
        size_t o = ((size_t)(k0>>1) + pr)*128 + c0 + cb4;
        wh4 = *(const uint4*)(wph + o);
        wl4 = *(const uint4*)(wpl + o);
    };
    auto loadA = [&](int k0){
        const float* asrc;
        if (MODE == 0) {
            asrc = A + (size_t)(m0 + ar)*128 + k0 + ao;
        } else if (MODE == 1) {
            int seg = k0 >> 7, col = k0 & 127;
            asrc = A + (size_t)s_src[seg][ar]*128 + col + ao;
        } else {
            int seg = k0 >> 7, col = k0 & 127;
            const float* base = seg ? A2 : A;
            asrc = base + (size_t)(m0 + ar)*128 + col + ao;
        }
        a0 = *(const float4*)(asrc + 0);
        a1 = *(const float4*)(asrc + 4);
        a2 = *(const float4*)(asrc + 8);
        a3 = *(const float4*)(asrc + 12);
    };

    loadW(0); loadA(0);

    for (int k0 = 0; k0 < KTOT; k0 += 32) {
        __syncthreads();
        *(uint4*)(Wph + pr*PST2 + cb4) = wh4;
        *(uint4*)(Wpl + pr*PST2 + cb4) = wl4;
        {
            float* d = As + ar*ASTRIDE + ao;
            *(float4*)(d + 0)  = a0;
            *(float4*)(d + 4)  = a1;
            *(float4*)(d + 8)  = a2;
            *(float4*)(d + 12) = a3;
        }
        __syncthreads();

        if (k0 + 32 < KTOT) { loadW(k0 + 32); loadA(k0 + 32); }

        #pragma unroll
        for (int kc = 0; kc < 2; ++kc) {
            const float* ap  = As + (16*w + g)*ASTRIDE + kc*16;
            const float* ap8 = ap + 8*ASTRIDE;
            float2 x0 = *(const float2*)(ap  + 2*l);
            float2 x1 = *(const float2*)(ap8 + 2*l);
            float2 x2 = *(const float2*)(ap  + 2*l + 8);
            float2 x3 = *(const float2*)(ap8 + 2*l + 8);
            uint32_t ah[4], al[4];
            ah[0] = packsplit(x0.x, x0.y, al[0]);
            ah[1] = packsplit(x1.x, x1.y, al[1]);
            ah[2] = packsplit(x2.x, x2.y, al[2]);
            ah[3] = packsplit(x3.x, x3.y, al[3]);
            const uint32_t* ph  = Wph + (kc*8 + l)*PST2;
            const uint32_t* ph4 = Wph + (kc*8 + l + 4)*PST2;
            const uint32_t* pl  = Wpl + (kc*8 + l)*PST2;
            const uint32_t* pl4 = Wpl + (kc*8 + l + 4)*PST2;
            #pragma unroll
            for (int nt = 0; nt < 8; ++nt) {
                int dcol = nt*8 + g;
                uint32_t bh0 = ph[dcol],  bh1 = ph4[dcol];
                uint32_t bl0 = pl[dcol],  bl1 = pl4[dcol];
                mma_f16(acc[nt], ah, bh0, bh1);
                mma_f16(acc[nt], al, bh0, bh1);
                mma_f16(acc[nt], ah, bl0, bl1);
            }
        }
    }

    const int r0 = 16*w + g;
    const int o0 = s_out[r0], o1 = s_out[r0 + 8];
    float* w0 = out + (size_t)o0*128;
    float* w1 = out + (size_t)o1*128;
    #pragma unroll
    for (int nt = 0; nt < 8; ++nt) {
        int col = c0 + nt*8 + 2*l;
        float b0 = __ldg(bias + col), b1 = __ldg(bias + col + 1);
        if (o0 >= 0) *(float2*)(w0 + col) = make_float2(acc[nt][0]+b0, acc[nt][1]+b1);
        if (o1 >= 0) *(float2*)(w1 + col) = make_float2(acc[nt][2]+b0, acc[nt][3]+b1);
    }
}

// ======== fp16 mma attention, 1-product (Ph x Vh), j-split x2: grid(32,B), 256 thr ========
__device__ __forceinline__ float pval(float q, float M, float kv, float mv){
    float x = q + kv; x = x > 0.f ? x : 0.01f*x;
    return __expf(x*mv - M);
}
__device__ __forceinline__ float mval(const float* mrow, bool in, int gi, int j){
    return (in && j < Nn) ? __ldg(mrow + j) : ((gi == j) ? 1.f : 0.f);
}

__global__ void __launch_bounds__(256) attn_mma_kernel(
    const uint32_t* __restrict__ vph,
    const float* __restrict__ qs, const float* __restrict__ ks,
    const float* __restrict__ ksmax, const float* __restrict__ mask,
    float* __restrict__ num, float* __restrict__ den)
{
    __shared__ uint32_t Vph[16*PSTR];
    __shared__ float s_ks[32];

    const int b = blockIdx.y;
    const int jc = blockIdx.x & 1;
    const int i0 = (blockIdx.x >> 1) * 128;
    const int tid = threadIdx.x, w = tid>>5, lane = tid&31;
    const int g = lane>>2, l = lane&3;
    const int r0 = 16*w + g, r1 = r0 + 8;
    const int gi0 = i0 + r0, gi1 = i0 + r1;

    const float q0 = qs[b*Cc + gi0];
    const float q1 = qs[b*Cc + gi1];
    const float km = ksmax[b];
    float t0 = q0 + km; t0 = t0 > 0.f ? t0 : 0.01f*t0;
    float t1 = q1 + km; t1 = t1 > 0.f ? t1 : 0.01f*t1;
    const float M0 = fmaxf(0.f, t0);
    const float M1 = fmaxf(0.f, t1);
    float sum0 = 0.f, sum1 = 0.f;

    const float* mrow0 = mask + (size_t)b*Nn*Nn + (size_t)gi0*Nn;
    const float* mrow1 = mask + (size_t)b*Nn*Nn + (size_t)gi1*Nn;
    const bool in0 = gi0 < Nn, in1 = gi1 < Nn;

    float acc[16][4];
    #pragma unroll
    for (int nt = 0; nt < 16; ++nt) {
        acc[nt][0]=0.f; acc[nt][1]=0.f; acc[nt][2]=0.f; acc[nt][3]=0.f;
    }

    const int pr = tid>>4, cb = (tid&15)*8;
    const int jbeg = jc * 1024, jend = jbeg + 1024;

    uint4 vhA, vhB;
    float ksr = 0.f;
    auto loadV = [&](int j0){
        size_t o = ((size_t)((b*Cc + j0) >> 1) + pr)*128 + cb;
        vhA = *(const uint4*)(vph + o);
        vhB = *(const uint4*)(vph + o + 4);
        if (tid < 32) ksr = ks[b*Cc + j0 + tid];
    };
    loadV(jbeg);

    for (int j0 = jbeg; j0 < jend; j0 += 32) {
        __syncthreads();
        *(uint4*)(Vph + pr*PSTR + cb)     = vhA;
        *(uint4*)(Vph + pr*PSTR + cb + 4) = vhB;
        if (tid < 32) s_ks[tid] = ksr;
        __syncthreads();

        if (j0 + 32 < jend) loadV(j0 + 32);

        float m0v[8], m1v[8];
        #pragma unroll
        for (int kc = 0; kc < 2; ++kc) {
            int ja = j0 + kc*16 + 2*l;
            m0v[kc*4+0] = mval(mrow0, in0, gi0, ja);
            m0v[kc*4+1] = mval(mrow0, in0, gi0, ja+1);
            m0v[kc*4+2] = mval(mrow0, in0, gi0, ja+8);
            m0v[kc*4+3] = mval(mrow0, in0, gi0, ja+9);
            m1v[kc*4+0] = mval(mrow1, in1, gi1, ja);
            m1v[kc*4+1] = mval(mrow1, in1, gi1, ja+1);
            m1v[kc*4+2] = mval(mrow1, in1, gi1, ja+8);
            m1v[kc*4+3] = mval(mrow1, in1, gi1, ja+9);
        }

        #pragma unroll
        for (int kc = 0; kc < 2; ++kc) {
            const int kb = kc*16 + 2*l;
            const float kv0 = s_ks[kb],   kv1 = s_ks[kb+1];
            const float kv8 = s_ks[kb+8], kv9 = s_ks[kb+9];
            float p00 = pval(q0, M0, kv0, m0v[kc*4+0]);
            float p01 = pval(q0, M0, kv1, m0v[kc*4+1]);
            float p08 = pval(q0, M0, kv8, m0v[kc*4+2]);
            float p09 = pval(q0, M0, kv9, m0v[kc*4+3]);
            float p10 = pval(q1, M1, kv0, m1v[kc*4+0]);
            float p11 = pval(q1, M1, kv1, m1v[kc*4+1]);
            float p18 = pval(q1, M1, kv8, m1v[kc*4+2]);
            float p19 = pval(q1, M1, kv9, m1v[kc*4+3]);
            sum0 += p00 + p01 + p08 + p09;
            sum1 += p10 + p11 + p18 + p19;
            uint32_t ah[4];
            ah[0] = packh2(p00, p01);
            ah[1] = packh2(p10, p11);
            ah[2] = packh2(p08, p09);
            ah[3] = packh2(p18, p19);
            const uint32_t* ph  = Vph + (kc*8 + l)*PSTR;
            const uint32_t* ph4 = Vph + (kc*8 + l + 4)*PSTR;
            #pragma unroll
            for (int nt = 0; nt < 16; ++nt) {
                int dcol = nt*8 + g;
                mma_f16(acc[nt], ah, ph[dcol], ph4[dcol]);
            }
        }
    }

    sum0 += __shfl_xor_sync(0xffffffffu, sum0, 1);
    sum0 += __shfl_xor_sync(0xffffffffu, sum0, 2);
    sum1 += __shfl_xor_sync(0xffffffffu, sum1, 1);
    sum1 += __shfl_xor_sync(0xffffffffu, sum1, 2);
    if (l == 0) {
        den[(size_t)jc*BC + b*Cc + gi0] = sum0;
        den[(size_t)jc*BC + b*Cc + gi1] = sum1;
    }

    float* n0 = num + (size_t)jc*BC*Dd + ((size_t)(b*Cc + gi0))*128;
    float* n1 = num + (size_t)jc*BC*Dd + ((size_t)(b*Cc + gi1))*128;
    #pragma unroll
    for (int nt = 0; nt < 16; ++nt) {
        int col = nt*8 + 2*l;
        *(float2*)(n0 + col) = make_float2(acc[nt][0], acc[nt][1]);
        *(float2*)(n1 + col) = make_float2(acc[nt][2], acc[nt][3]);
    }
}

__global__ void __launch_bounds__(256) combine_kernel(
    const float* __restrict__ num, const float* __restrict__ den,
    float* __restrict__ wt)
{
    size_t idx = (size_t)blockIdx.x*256 + threadIdx.x;
    int m = (int)(idx >> 7);
    float d = den[m] + den[BC + m];
    wt[idx] = (num[idx] + num[(size_t)BC*Dd + idx]) / d;
}

__global__ void __launch_bounds__(128) fixup_kernel(
    const float* __restrict__ v, const float* __restrict__ part,
    const float* __restrict__ qs, const float* __restrict__ ks,
    float* __restrict__ weighted)
{
    int b = blockIdx.x, which = blockIdx.y, tx = threadIdx.x;
    int r = Nn + which;
    float vsum = 0.f;
    #pragma unroll
    for (int p = 0; p < 16; ++p) vsum += part[(b*16 + p)*128 + tx];
    float s = qs[b*Cc + r] + ks[b*Cc + r];
    s = s > 0.f ? s : 0.01f*s;
    float mx = fmaxf(s, 0.f);
    float es = __expf(s - mx), e0 = __expf(-mx);
    float vr = v[((size_t)(b*Cc + r))*128 + tx];
    float denom = es + (float)(Cc - 1) * e0;
    weighted[((size_t)(b*Cc + r))*128 + tx] = (es*vr + e0*(vsum - vr)) / denom;
}

__global__ void __launch_bounds__(128) mean1_kernel(const float* __restrict__ f, float* __restrict__ part){
    int b = blockIdx.x, p = blockIdx.y, tx = threadIdx.x;
    float s = 0.f;
    #pragma unroll 8
    for (int i = 0; i < Cc/16; ++i) s += f[((size_t)b*Cc + p*(Cc/16) + i)*128 + tx];
    part[(b*16 + p)*128 + tx] = s;
}
__global__ void __launch_bounds__(128) mean2_kernel(const float* __restrict__ part, float* __restrict__ out){
    int b = blockIdx.x, tx = threadIdx.x;
    float s = 0.f;
    #pragma unroll
    for (int p = 0; p < 16; ++p) s += part[(b*16 + p)*128 + tx];
    out[b*128 + tx] = s * (1.f/Cc);
}

extern "C" void kernel_launch(void* const* d_in, const int* in_sizes, int n_in,
                              void* d_out, int out_size)
{
    const float* ops       = (const float*)d_in[0];
    const float* mask      = (const float*)d_in[1];
    const int*   relations = (const int*)d_in[2];
    const int*   begins    = (const int*)d_in[3];
    const int*   ends      = (const int*)d_in[4];
    const float* init_bp_w = (const float*)d_in[5];
    const float* init_bp_b = (const float*)d_in[6];
    const float* init_ep_w = (const float*)d_in[7];
    const float* init_ep_b = (const float*)d_in[8];
    const float* be_bp_w   = (const float*)d_in[9];
    const float* be_bp_b   = (const float*)d_in[10];
    const float* be_ep_w   = (const float*)d_in[11];
    const float* be_ep_b   = (const float*)d_in[12];
    const float* seq_mix_w = (const float*)d_in[13];
    const float* seq_mix_b = (const float*)d_in[14];
    const float* attn_w_w  = (const float*)d_in[15];
    const float* attn_w_b  = (const float*)d_in[16];
    const float* score_w   = (const float*)d_in[17];
    const float* score_b   = (const float*)d_in[18];
    const float* attn_out_w= (const float*)d_in[19];
    const float* attn_out_b= (const float*)d_in[20];
    const float* mix_w     = (const float*)d_in[21];
    const float* mix_b     = (const float*)d_in[22];
    float* out = (float*)d_out;

    float *p_f0,*p_f1,*p_v,*p_seq,*p_wt,*p_qs,*p_ks,*p_uq,*p_uk,*p_c,*p_part,*p_km,*p_num,*p_den,*p_wf,*p_wfb;
    uint32_t *p_wph,*p_wpl,*p_vph;
    cudaGetSymbolAddress((void**)&p_f0, g_feats0);
    cudaGetSymbolAddress((void**)&p_f1, g_feats1);
    cudaGetSymbolAddress((void**)&p_v,  g_v);
    cudaGetSymbolAddress((void**)&p_seq, g_seq);
    cudaGetSymbolAddress((void**)&p_wt, g_weighted);
    cudaGetSymbolAddress((void**)&p_qs, g_qs);
    cudaGetSymbolAddress((void**)&p_ks, g_ks);
    cudaGetSymbolAddress((void**)&p_uq, g_uq);
    cudaGetSymbolAddress((void**)&p_uk, g_uk);
    cudaGetSymbolAddress((void**)&p_c,  g_c);
    cudaGetSymbolAddress((void**)&p_part, g_part);
    cudaGetSymbolAddress((void**)&p_km, g_ksmax);
    cudaGetSymbolAddress((void**)&p_num, g_num);
    cudaGetSymbolAddress((void**)&p_den, g_den);
    cudaGetSymbolAddress((void**)&p_wf, g_wf);
    cudaGetSymbolAddress((void**)&p_wfb, g_wfb);
    cudaGetSymbolAddress((void**)&p_wph, g_wph);
    cudaGetSymbolAddress((void**)&p_wpl, g_wpl);
    cudaGetSymbolAddress((void**)&p_vph, g_vph);

    copy_ops_kernel<<<(BN*Dd)/256, 256>>>(ops, p_f0);
    begin_end_kernel<<<dim3(Bb,2), 128>>>(p_f0, begins, ends,
        init_bp_w, init_bp_b, init_ep_w, init_ep_b, p_f0);
    fuseW_kernel<<<dim3(129,2), 128>>>(attn_out_w, attn_out_b, mix_w, mix_b, p_wf, p_wfb);
    packAllW_kernel<<<(2*384*128)/256, 256>>>(attn_w_w, seq_mix_w, mix_w, p_wf,
                                              p_wph, p_wpl);

    for (int l = 0; l < Ll; ++l) {
        float* cur = (l == 0) ? p_f0 : p_f1;
        float* nxt = (l == 0) ? p_f1 : (out + Bb*Dd);
        size_t base = (size_t)l*384*128;

        precompute2_kernel<<<130, 32>>>(attn_w_w + (size_t)l*128*384, attn_w_b + (size_t)l*384,
                                        score_w + (size_t)l*256, score_b + l, p_uq, p_uk, p_c);
        qsks_kernel<<<BC/8, 256>>>(cur, p_uq, p_uk, p_c, p_qs, p_ks);
        ksmax_kernel<<<Bb, 256>>>(p_ks, p_km);

        gemm_mma_kernel<0,128><<<dim3(BC/128,2), 256>>>(cur, nullptr,
            p_wph + base, p_wpl + base, attn_w_b + (size_t)l*384 + 256, p_v, nullptr);
        packVmean_kernel<<<dim3(Bb,16), 128>>>(p_v, p_vph, p_part);

        begin_end_kernel<<<dim3(Bb,2), 128>>>(cur, begins, ends,
            be_bp_w + (size_t)l*128*128, be_bp_b + (size_t)l*128,
            be_ep_w + (size_t)l*128*128, be_ep_b + (size_t)l*128, p_seq);

        gemm_mma_kernel<1,384><<<dim3(BC/128,2), 256>>>(cur, nullptr,
            p_wph + base + (size_t)64*128, p_wpl + base + (size_t)64*128,
            seq_mix_b + (size_t)l*128, p_seq, relations);

        attn_mma_kernel<<<dim3(32, Bb), 256>>>(p_vph, p_qs, p_ks, p_km, mask, p_num, p_den);
        combine_kernel<<<(BC*Dd)/256, 256>>>(p_num, p_den, p_wt);
        fixup_kernel<<<dim3(Bb,2), 128>>>(p_v, p_part, p_qs, p_ks, p_wt);

        gemm_mma_kernel<2,256><<<dim3(BC/128,2), 256>>>(p_seq, p_wt,
            p_wph + base + (size_t)256*128, p_wpl + base + (size_t)256*128,
            p_wfb + l*128, nxt, nullptr);
    }

    mean1_kernel<<<dim3(Bb,16), 128>>>(out + Bb*Dd, p_part);
    mean2_kernel<<<Bb, 128>>>(p_part, out);
}